// round 10
// baseline (speedup 1.0000x reference)
#include <cuda_runtime.h>

// DeepFilter: out_r = box3x5( xr*fr - xi*fi ),  out_i = 2 * box3x5( xr*fi )
// Smem-free: time halo via warp shuffles, freq via rolling 3-row window.
// R10: each warp covers 8 d-rows x 64 t-cols (lane holds float2) -> total
// warps double to 8192 (55 warps/SM offered) with unchanged 1.25x read
// amplification. Occupancy was the binding constraint in the L2-warm
// timed regime; this doubles latency-hiding capacity.
// Shapes: B=8, D=256, T=2048, L=2, I=1. Output [B, 2D, T].

static constexpr int Bn = 8;
static constexpr int Dn = 256;
static constexpr int Tn = 2048;

static constexpr int NTHREADS = 128;   // 4 warps: 2 in d x 2 in t
static constexpr int T_TILE   = 128;   // block covers 128 t-cols (2 x 64)
static constexpr int T_WARP   = 64;    // t-cols per warp (lane holds float2)
static constexpr int D_STRIP  = 8;     // output d-rows per warp
static constexpr int D_TILE   = 16;    // block covers 16 d-rows (2 x 8)

__device__ __forceinline__ float2 ld2(const float* p) {
    return *reinterpret_cast<const float2*>(p);
}

__global__ __launch_bounds__(NTHREADS, 12)
void deepfilter_kernel(const float* __restrict__ xr,
                       const float* __restrict__ xi,
                       const float* __restrict__ fr,
                       const float* __restrict__ fi,
                       float* __restrict__ out)
{
    const int b    = blockIdx.z;
    const int t0   = blockIdx.x * T_TILE;
    const int d0   = blockIdx.y * D_TILE;
    const int warp = threadIdx.x >> 5;
    const int lane = threadIdx.x & 31;
    const int wd   = warp >> 1;            // d-group within block
    const int wt   = warp & 1;             // t-half within block
    const int wt0  = t0 + T_WARP * wt;     // warp's t base
    const int t    = wt0 + 2 * lane;       // lane's 2 cols: t, t+1

    const size_t base  = (size_t)b * Dn * Tn;
    const int    dbase = d0 + D_STRIP * wd;   // output rows dbase .. dbase+7

    // Warp-edge time halo: lane 0 needs cols wt0-2,wt0-1; lane 31 needs
    // wt0+64,wt0+65. Both are 8B-aligned float2 loads used identically.
    const int  ht    = (lane == 0) ? (wt0 - 2) : (wt0 + T_WARP);
    const bool hlane = (lane == 0) | (lane == 31);
    const bool hok_t = (ht >= 0) & (ht < Tn);

    // rolling time-sum state: s[r-1], s[r-2]
    float2 m1r = {0,0}, m1i = {0,0};
    float2 m2r = {0,0}, m2i = {0,0};

    const size_t ob = (size_t)b * (2 * Dn) * Tn;
    const size_t oI = (size_t)Dn * Tn;

    #pragma unroll
    for (int r = 0; r < D_STRIP + 2; ++r) {
        const int  d   = dbase - 1 + r;
        const bool dok = (unsigned)d < (unsigned)Dn;

        float2 a = {0,0}, c = {0,0}, e = {0,0}, f = {0,0};
        float2 ha = {0,0}, hc = {0,0}, he = {0,0}, hf = {0,0};

        if (dok) {
            const size_t idx = base + (size_t)d * Tn + t;
            a = ld2(xr + idx); c = ld2(xi + idx);
            e = ld2(fr + idx); f = ld2(fi + idx);
            if (hlane & hok_t) {
                const size_t hidx = base + (size_t)d * Tn + ht;
                ha = ld2(xr + hidx); hc = ld2(xi + hidx);
                he = ld2(fr + hidx); hf = ld2(fi + hidx);
            }
        }

        // pointwise products (imag WITHOUT the 2x — folded into store)
        const float pr0 = fmaf(a.x, e.x, -c.x * f.x);
        const float pr1 = fmaf(a.y, e.y, -c.y * f.y);
        const float pi0 = a.x * f.x;
        const float pi1 = a.y * f.y;

        // halo products (lane0: t-2,t-1 ; lane31: t+2.. at warp edge)
        const float hpr0 = fmaf(ha.x, he.x, -hc.x * hf.x);
        const float hpr1 = fmaf(ha.y, he.y, -hc.y * hf.y);
        const float hpi0 = ha.x * hf.x;
        const float hpi1 = ha.y * hf.y;

        // neighbor exchange: lm* = p[-2],p[-1]; rp* = p[+2],p[+3]
        float lmr2 = __shfl_up_sync(0xffffffffu, pr0, 1);
        float lmr1 = __shfl_up_sync(0xffffffffu, pr1, 1);
        float rpr2 = __shfl_down_sync(0xffffffffu, pr0, 1);
        float rpr3 = __shfl_down_sync(0xffffffffu, pr1, 1);
        float lmi2 = __shfl_up_sync(0xffffffffu, pi0, 1);
        float lmi1 = __shfl_up_sync(0xffffffffu, pi1, 1);
        float rpi2 = __shfl_down_sync(0xffffffffu, pi0, 1);
        float rpi3 = __shfl_down_sync(0xffffffffu, pi1, 1);
        if (lane == 0)  { lmr2 = hpr0; lmr1 = hpr1; lmi2 = hpi0; lmi1 = hpi1; }
        if (lane == 31) { rpr2 = hpr0; rpr3 = hpr1; rpi2 = hpi0; rpi3 = hpi1; }

        // sliding 5-tap time sums for this input row (2 outputs per lane)
        float2 sr, si;
        sr.x = lmr2 + lmr1 + pr0 + pr1 + rpr2;
        sr.y = sr.x - lmr2 + rpr3;
        si.x = lmi2 + lmi1 + pi0 + pi1 + rpi2;
        si.y = si.x - lmi2 + rpi3;

        // rolling 3-row freq sum: emit output row dbase + r - 2
        if (r >= 2) {
            const int d_out = dbase + r - 2;
            float2 orr, oii;
            orr.x = m2r.x + m1r.x + sr.x;
            orr.y = m2r.y + m1r.y + sr.y;
            oii.x = 2.f * (m2i.x + m1i.x + si.x);
            oii.y = 2.f * (m2i.y + m1i.y + si.y);
            const size_t o = ob + (size_t)d_out * Tn + t;
            __stcs(reinterpret_cast<float2*>(out + o),      orr);
            __stcs(reinterpret_cast<float2*>(out + o + oI), oii);
        }
        m2r = m1r; m2i = m1i;
        m1r = sr;  m1i = si;
    }
}

extern "C" void kernel_launch(void* const* d_in, const int* in_sizes, int n_in,
                              void* d_out, int out_size)
{
    (void)in_sizes; (void)n_in; (void)out_size;
    const float* xr = (const float*)d_in[0];
    const float* xi = (const float*)d_in[1];
    const float* fr = (const float*)d_in[2];
    const float* fi = (const float*)d_in[3];
    float* out = (float*)d_out;

    dim3 grid(Tn / T_TILE, Dn / D_TILE, Bn);   // (16, 16, 8) = 2048 blocks
    deepfilter_kernel<<<grid, NTHREADS>>>(xr, xi, fr, fi, out);
}

// round 11
// speedup vs baseline: 1.5496x; 1.5496x over previous
#include <cuda_runtime.h>

// DeepFilter: out_r = box3x5( xr*fr - xi*fi ),  out_i = 2 * box3x5( xr*fi )
// (input and filter are shifted identically per tap in the reference, so the
//  15-tap "deep filter" is exactly a 3(freq) x 5(time) box sum of the
//  pointwise products, with zero padding.)
//
// Final configuration (verified best, 14.7 us):
//  - smem-free; time halo via warp shuffles; freq via rolling 3-row window
//  - each warp owns 8 output d-rows, streams 10 input rows (1.25x read amp)
//  - LDG.128 per array (512B in flight per warp-load: MLP in bytes is the
//    binding resource — narrower loads regressed 56%)
//  - 64 registers (fewer regs starve load batching; more is neutral)
//  - per-row predication retained: throttles LDG front-batching, avoiding
//    cross-CTA L1tex-queue contention (unpredicated interior regressed 22%)
// Shapes: B=8, D=256, T=2048, L=2, I=1. Output [B, 2D, T].

static constexpr int Bn = 8;
static constexpr int Dn = 256;
static constexpr int Tn = 2048;

static constexpr int NTHREADS = 128;   // 4 warps
static constexpr int T_TILE   = 128;   // 32 lanes x float4
static constexpr int D_STRIP  = 8;     // output rows per warp
static constexpr int D_TILE   = (NTHREADS / 32) * D_STRIP;   // 32 rows / block

__device__ __forceinline__ float4 ld4(const float* p) {
    return *reinterpret_cast<const float4*>(p);
}
__device__ __forceinline__ float2 ld2(const float* p) {
    return *reinterpret_cast<const float2*>(p);
}

__global__ __launch_bounds__(NTHREADS, 8)
void deepfilter_kernel(const float* __restrict__ xr,
                       const float* __restrict__ xi,
                       const float* __restrict__ fr,
                       const float* __restrict__ fi,
                       float* __restrict__ out)
{
    const int b    = blockIdx.z;
    const int t0   = blockIdx.x * T_TILE;
    const int d0   = blockIdx.y * D_TILE;
    const int warp = threadIdx.x >> 5;
    const int lane = threadIdx.x & 31;
    const int t    = t0 + 4 * lane;

    const size_t base  = (size_t)b * Dn * Tn;
    const int    dbase = d0 + D_STRIP * warp;   // output rows dbase .. dbase+7

    // Warp-edge time halo: lane 0 needs cols t0-2,t0-1; lane 31 needs
    // t0+128,t0+129. Both are 8B-aligned float2 loads used identically.
    const int  ht    = (lane == 0) ? (t0 - 2) : (t0 + T_TILE);
    const bool hlane = (lane == 0) | (lane == 31);
    const bool hok_t = (ht >= 0) & (ht < Tn);

    // rolling time-sum state: s[r-1], s[r-2]
    float4 m1r = {0,0,0,0}, m1i = {0,0,0,0};
    float4 m2r = {0,0,0,0}, m2i = {0,0,0,0};

    const size_t ob = (size_t)b * (2 * Dn) * Tn;
    const size_t oI = (size_t)Dn * Tn;

    #pragma unroll
    for (int r = 0; r < D_STRIP + 2; ++r) {
        const int  d   = dbase - 1 + r;
        const bool dok = (unsigned)d < (unsigned)Dn;

        float4 a = {0,0,0,0}, c = {0,0,0,0}, e = {0,0,0,0}, f = {0,0,0,0};
        float2 ha = {0,0}, hc = {0,0}, he = {0,0}, hf = {0,0};

        if (dok) {
            const size_t idx = base + (size_t)d * Tn + t;
            a = ld4(xr + idx); c = ld4(xi + idx);
            e = ld4(fr + idx); f = ld4(fi + idx);
            if (hlane & hok_t) {
                const size_t hidx = base + (size_t)d * Tn + ht;
                ha = ld2(xr + hidx); hc = ld2(xi + hidx);
                he = ld2(fr + hidx); hf = ld2(fi + hidx);
            }
        }

        // pointwise products (imag part WITHOUT the 2x — folded into store)
        const float pr0 = fmaf(a.x, e.x, -c.x * f.x);
        const float pr1 = fmaf(a.y, e.y, -c.y * f.y);
        const float pr2 = fmaf(a.z, e.z, -c.z * f.z);
        const float pr3 = fmaf(a.w, e.w, -c.w * f.w);
        const float pi0 = a.x * f.x;
        const float pi1 = a.y * f.y;
        const float pi2 = a.z * f.z;
        const float pi3 = a.w * f.w;

        // halo products (lane0: t-2,t-1 ; lane31: t+4,t+5)
        const float hpr0 = fmaf(ha.x, he.x, -hc.x * hf.x);
        const float hpr1 = fmaf(ha.y, he.y, -hc.y * hf.y);
        const float hpi0 = ha.x * hf.x;
        const float hpi1 = ha.y * hf.y;

        // neighbor exchange: lm* = p[-2],p[-1]; rp* = p[+4],p[+5]
        float lmr2 = __shfl_up_sync(0xffffffffu, pr2, 1);
        float lmr1 = __shfl_up_sync(0xffffffffu, pr3, 1);
        float rpr4 = __shfl_down_sync(0xffffffffu, pr0, 1);
        float rpr5 = __shfl_down_sync(0xffffffffu, pr1, 1);
        float lmi2 = __shfl_up_sync(0xffffffffu, pi2, 1);
        float lmi1 = __shfl_up_sync(0xffffffffu, pi3, 1);
        float rpi4 = __shfl_down_sync(0xffffffffu, pi0, 1);
        float rpi5 = __shfl_down_sync(0xffffffffu, pi1, 1);
        if (lane == 0)  { lmr2 = hpr0; lmr1 = hpr1; lmi2 = hpi0; lmi1 = hpi1; }
        if (lane == 31) { rpr4 = hpr0; rpr5 = hpr1; rpi4 = hpi0; rpi5 = hpi1; }

        // sliding 5-tap time sums for this input row
        float4 sr, si;
        sr.x = lmr2 + lmr1 + pr0 + pr1 + pr2;
        sr.y = sr.x - lmr2 + pr3;
        sr.z = sr.y - lmr1 + rpr4;
        sr.w = sr.z - pr0 + rpr5;
        si.x = lmi2 + lmi1 + pi0 + pi1 + pi2;
        si.y = si.x - lmi2 + pi3;
        si.z = si.y - lmi1 + rpi4;
        si.w = si.z - pi0 + rpi5;

        // rolling 3-row freq sum: emit output row dbase + r - 2
        if (r >= 2) {
            const int d_out = dbase + r - 2;
            float4 orr, oii;
            orr.x = m2r.x + m1r.x + sr.x;
            orr.y = m2r.y + m1r.y + sr.y;
            orr.z = m2r.z + m1r.z + sr.z;
            orr.w = m2r.w + m1r.w + sr.w;
            oii.x = 2.f * (m2i.x + m1i.x + si.x);
            oii.y = 2.f * (m2i.y + m1i.y + si.y);
            oii.z = 2.f * (m2i.z + m1i.z + si.z);
            oii.w = 2.f * (m2i.w + m1i.w + si.w);
            const size_t o = ob + (size_t)d_out * Tn + t;
            __stcs(reinterpret_cast<float4*>(out + o),      orr);
            __stcs(reinterpret_cast<float4*>(out + o + oI), oii);
        }
        m2r = m1r; m2i = m1i;
        m1r = sr;  m1i = si;
    }
}

extern "C" void kernel_launch(void* const* d_in, const int* in_sizes, int n_in,
                              void* d_out, int out_size)
{
    (void)in_sizes; (void)n_in; (void)out_size;
    const float* xr = (const float*)d_in[0];
    const float* xi = (const float*)d_in[1];
    const float* fr = (const float*)d_in[2];
    const float* fi = (const float*)d_in[3];
    float* out = (float*)d_out;

    dim3 grid(Tn / T_TILE, Dn / D_TILE, Bn);   // (16, 8, 8) = 1024 blocks
    deepfilter_kernel<<<grid, NTHREADS>>>(xr, xi, fr, fi, out);
}

// round 12
// speedup vs baseline: 1.5529x; 1.0022x over previous
#include <cuda_runtime.h>

// DeepFilter: out_r = box3x5( xr*fr - xi*fi ),  out_i = 2 * box3x5( xr*fi )
// 3(freq) x 5(time) box sum of pointwise products with zero padding.
//
// R12: explicit one-row software pipeline over the R4 optimum. Each
// iteration prefetches the NEXT row's four LDG.128s before computing on
// the current row, hiding load latency behind the ~150cyc iteration body.
// MLP bounded at ~2 rows in flight (avoids the R5 front-batch contention).
// Shapes: B=8, D=256, T=2048, L=2, I=1. Output [B, 2D, T].

static constexpr int Bn = 8;
static constexpr int Dn = 256;
static constexpr int Tn = 2048;

static constexpr int NTHREADS = 128;   // 4 warps
static constexpr int T_TILE   = 128;   // 32 lanes x float4
static constexpr int D_STRIP  = 8;     // output rows per warp
static constexpr int D_TILE   = (NTHREADS / 32) * D_STRIP;   // 32 rows / block

__device__ __forceinline__ float4 ld4(const float* p) {
    return *reinterpret_cast<const float4*>(p);
}
__device__ __forceinline__ float2 ld2(const float* p) {
    return *reinterpret_cast<const float2*>(p);
}

__global__ __launch_bounds__(NTHREADS, 7)
void deepfilter_kernel(const float* __restrict__ xr,
                       const float* __restrict__ xi,
                       const float* __restrict__ fr,
                       const float* __restrict__ fi,
                       float* __restrict__ out)
{
    const int b    = blockIdx.z;
    const int t0   = blockIdx.x * T_TILE;
    const int d0   = blockIdx.y * D_TILE;
    const int warp = threadIdx.x >> 5;
    const int lane = threadIdx.x & 31;
    const int t    = t0 + 4 * lane;

    const size_t base  = (size_t)b * Dn * Tn;
    const int    dbase = d0 + D_STRIP * warp;   // output rows dbase .. dbase+7

    // Warp-edge time halo: lane 0 needs cols t0-2,t0-1; lane 31 needs
    // t0+128,t0+129. Both are 8B-aligned float2 loads used identically.
    const int  ht    = (lane == 0) ? (t0 - 2) : (t0 + T_TILE);
    const bool hlane = (lane == 0) | (lane == 31);
    const bool hok_t = (ht >= 0) & (ht < Tn);

    // rolling time-sum state: s[r-1], s[r-2]
    float4 m1r = {0,0,0,0}, m1i = {0,0,0,0};
    float4 m2r = {0,0,0,0}, m2i = {0,0,0,0};

    const size_t ob = (size_t)b * (2 * Dn) * Tn;
    const size_t oI = (size_t)Dn * Tn;

    // ---- prologue: load row r=0 (d = dbase-1) ----
    float4 a = {0,0,0,0}, c = {0,0,0,0}, e = {0,0,0,0}, f = {0,0,0,0};
    {
        const int d = dbase - 1;
        if ((unsigned)d < (unsigned)Dn) {
            const size_t idx = base + (size_t)d * Tn + t;
            a = ld4(xr + idx); c = ld4(xi + idx);
            e = ld4(fr + idx); f = ld4(fi + idx);
        }
    }

    #pragma unroll
    for (int r = 0; r < D_STRIP + 2; ++r) {
        const int d = dbase - 1 + r;   // current row (data already in a,c,e,f)

        // ---- prefetch NEXT row's main loads (issued before any use of cur) ----
        float4 na = {0,0,0,0}, nc = {0,0,0,0}, ne = {0,0,0,0}, nf = {0,0,0,0};
        if (r < D_STRIP + 1) {
            const int dn_ = dbase + r;      // = (dbase-1) + (r+1)
            if ((unsigned)dn_ < (unsigned)Dn) {
                const size_t nidx = base + (size_t)dn_ * Tn + t;
                na = ld4(xr + nidx); nc = ld4(xi + nidx);
                ne = ld4(fr + nidx); nf = ld4(fi + nidx);
            }
        }

        // ---- current row's halo loads (2 lanes; L1/L2-hit) ----
        float2 ha = {0,0}, hc = {0,0}, he = {0,0}, hf = {0,0};
        if (((unsigned)d < (unsigned)Dn) & hlane & hok_t) {
            const size_t hidx = base + (size_t)d * Tn + ht;
            ha = ld2(xr + hidx); hc = ld2(xi + hidx);
            he = ld2(fr + hidx); hf = ld2(fi + hidx);
        }

        // pointwise products (imag part WITHOUT the 2x — folded into store)
        const float pr0 = fmaf(a.x, e.x, -c.x * f.x);
        const float pr1 = fmaf(a.y, e.y, -c.y * f.y);
        const float pr2 = fmaf(a.z, e.z, -c.z * f.z);
        const float pr3 = fmaf(a.w, e.w, -c.w * f.w);
        const float pi0 = a.x * f.x;
        const float pi1 = a.y * f.y;
        const float pi2 = a.z * f.z;
        const float pi3 = a.w * f.w;

        // halo products (lane0: t-2,t-1 ; lane31: t+4,t+5)
        const float hpr0 = fmaf(ha.x, he.x, -hc.x * hf.x);
        const float hpr1 = fmaf(ha.y, he.y, -hc.y * hf.y);
        const float hpi0 = ha.x * hf.x;
        const float hpi1 = ha.y * hf.y;

        // neighbor exchange: lm* = p[-2],p[-1]; rp* = p[+4],p[+5]
        float lmr2 = __shfl_up_sync(0xffffffffu, pr2, 1);
        float lmr1 = __shfl_up_sync(0xffffffffu, pr3, 1);
        float rpr4 = __shfl_down_sync(0xffffffffu, pr0, 1);
        float rpr5 = __shfl_down_sync(0xffffffffu, pr1, 1);
        float lmi2 = __shfl_up_sync(0xffffffffu, pi2, 1);
        float lmi1 = __shfl_up_sync(0xffffffffu, pi3, 1);
        float rpi4 = __shfl_down_sync(0xffffffffu, pi0, 1);
        float rpi5 = __shfl_down_sync(0xffffffffu, pi1, 1);
        if (lane == 0)  { lmr2 = hpr0; lmr1 = hpr1; lmi2 = hpi0; lmi1 = hpi1; }
        if (lane == 31) { rpr4 = hpr0; rpr5 = hpr1; rpi4 = hpi0; rpi5 = hpi1; }

        // sliding 5-tap time sums for this input row
        float4 sr, si;
        sr.x = lmr2 + lmr1 + pr0 + pr1 + pr2;
        sr.y = sr.x - lmr2 + pr3;
        sr.z = sr.y - lmr1 + rpr4;
        sr.w = sr.z - pr0 + rpr5;
        si.x = lmi2 + lmi1 + pi0 + pi1 + pi2;
        si.y = si.x - lmi2 + pi3;
        si.z = si.y - lmi1 + rpi4;
        si.w = si.z - pi0 + rpi5;

        // rolling 3-row freq sum: emit output row dbase + r - 2
        if (r >= 2) {
            const int d_out = dbase + r - 2;
            float4 orr, oii;
            orr.x = m2r.x + m1r.x + sr.x;
            orr.y = m2r.y + m1r.y + sr.y;
            orr.z = m2r.z + m1r.z + sr.z;
            orr.w = m2r.w + m1r.w + sr.w;
            oii.x = 2.f * (m2i.x + m1i.x + si.x);
            oii.y = 2.f * (m2i.y + m1i.y + si.y);
            oii.z = 2.f * (m2i.z + m1i.z + si.z);
            oii.w = 2.f * (m2i.w + m1i.w + si.w);
            const size_t o = ob + (size_t)d_out * Tn + t;
            __stcs(reinterpret_cast<float4*>(out + o),      orr);
            __stcs(reinterpret_cast<float4*>(out + o + oI), oii);
        }
        m2r = m1r; m2i = m1i;
        m1r = sr;  m1i = si;

        // rotate the pipeline
        a = na; c = nc; e = ne; f = nf;
    }
}

extern "C" void kernel_launch(void* const* d_in, const int* in_sizes, int n_in,
                              void* d_out, int out_size)
{
    (void)in_sizes; (void)n_in; (void)out_size;
    const float* xr = (const float*)d_in[0];
    const float* xi = (const float*)d_in[1];
    const float* fr = (const float*)d_in[2];
    const float* fi = (const float*)d_in[3];
    float* out = (float*)d_out;

    dim3 grid(Tn / T_TILE, Dn / D_TILE, Bn);   // (16, 8, 8) = 1024 blocks
    deepfilter_kernel<<<grid, NTHREADS>>>(xr, xi, fr, fi, out);
}